// round 10
// baseline (speedup 1.0000x reference)
#include <cuda_runtime.h>

// OT_Loss (Sinkhorn, N=9216, B=8, 100 iters) via separable-kernel factorization.
// dis[p,q] = E[pb,jy] + E[pa,jx]  =>  K = G (x) G with G = exp(-E/10), E 96x96.
// Each N x N matvec = two 96x96x96 fp32 GEMMs. One CTA per batch, all-SMEM.

#define D_       96
#define N_       9216
#define B_       8
#define NITER_   100
#define STR_     98
#define THREADS_ 256
#define SMEM_BYTES_ (5 * D_ * STR_ * sizeof(float))   // 188160 B

__device__ float g_G  [D_ * D_];    // G[i][j]
__device__ float g_GT [D_ * D_];    // G[j][i]
__device__ float g_HT [D_ * D_];    // H^T: g_HT[j][i] = (E*G)[i][j]
__device__ float g_src[B_ * N_];    // softmax(-unnormed)  (= b)
__device__ float g_tgt[B_ * N_];    // softmax(-gt)        (= a)
__device__ float g_partial[B_][3];  // per-batch (loss, wd, ot)

// ---------------- f32x2 helpers ----------------
__device__ __forceinline__ unsigned long long dup2(float x) {
    unsigned long long d;
    asm("mov.b64 %0, {%1, %1};" : "=l"(d) : "f"(x));
    return d;
}
__device__ __forceinline__ unsigned long long fma2(unsigned long long a,
                                                   unsigned long long b,
                                                   unsigned long long c) {
    unsigned long long d;
    asm("fma.rn.f32x2 %0, %1, %2, %3;" : "=l"(d) : "l"(a), "l"(b), "l"(c));
    return d;
}
__device__ __forceinline__ float2 unpack2(unsigned long long v) {
    float2 r;
    asm("mov.b64 {%0, %1}, %2;" : "=f"(r.x), "=f"(r.y) : "l"(v));
    return r;
}
__device__ __forceinline__ unsigned long long ld2(const float* p) {
    return *reinterpret_cast<const unsigned long long*>(p);
}

// ---------------- 96x96x96 TN GEMM: C[m,n] = sum_k A[k][m]*B[k][n] -----------
// Thread tile: 12 m-rows (6 f32x2 pairs) x 3 n-cols. warp -> m0, lane -> n0.
__device__ __forceinline__ void gemm_core(const float* __restrict__ A,
                                          const float* __restrict__ Bm,
                                          int m0, int n0,
                                          unsigned long long acc[6][3]) {
#pragma unroll
    for (int t = 0; t < 6; t++)
#pragma unroll
        for (int j = 0; j < 3; j++) acc[t][j] = 0ULL;

    const float* ap = A + m0;   // even offset -> 8B aligned; warp-broadcast
    const float* bp = Bm + n0;  // conflict-free (3*lane mod 32 is a bijection)
#pragma unroll 2
    for (int k = 0; k < D_; k++) {
        unsigned long long a[6];
#pragma unroll
        for (int t = 0; t < 6; t++) a[t] = ld2(ap + 2 * t);
        unsigned long long b0 = dup2(bp[0]);
        unsigned long long b1 = dup2(bp[1]);
        unsigned long long b2 = dup2(bp[2]);
#pragma unroll
        for (int t = 0; t < 6; t++) {
            acc[t][0] = fma2(a[t], b0, acc[t][0]);
            acc[t][1] = fma2(a[t], b1, acc[t][1]);
            acc[t][2] = fma2(a[t], b2, acc[t][2]);
        }
        ap += STR_;
        bp += STR_;
    }
}

__device__ __forceinline__ void store_plain(float* __restrict__ C, int m0, int n0,
                                            unsigned long long acc[6][3]) {
#pragma unroll
    for (int t = 0; t < 6; t++)
#pragma unroll
        for (int j = 0; j < 3; j++) {
            float2 v = unpack2(acc[t][j]);
            C[(m0 + 2 * t)     * STR_ + n0 + j] = v.x;
            C[(m0 + 2 * t + 1) * STR_ + n0 + j] = v.y;
        }
}

__device__ __forceinline__ float dot_tile(unsigned long long acc[6][3],
                                          const float* __restrict__ Um,
                                          int m0, int n0) {
    float s = 0.f;
#pragma unroll
    for (int t = 0; t < 6; t++)
#pragma unroll
        for (int j = 0; j < 3; j++) {
            float2 v = unpack2(acc[t][j]);
            s += v.x * Um[(m0 + 2 * t)     * STR_ + n0 + j];
            s += v.y * Um[(m0 + 2 * t + 1) * STR_ + n0 + j];
        }
    return s;
}

__device__ __forceinline__ float block_sum(float v, float* red) {
#pragma unroll
    for (int o = 16; o > 0; o >>= 1) v += __shfl_down_sync(0xffffffffu, v, o);
    __syncthreads();
    if ((threadIdx.x & 31) == 0) red[threadIdx.x >> 5] = v;
    __syncthreads();
    if (threadIdx.x == 0) {
        float s = 0.f;
#pragma unroll
        for (int i = 0; i < THREADS_ / 32; i++) s += red[i];
        v = s;
    }
    return v;  // valid on tid 0 only
}

// ---------------- precompute: softmaxes + G / G^T / H^T ----------------
__global__ void precompute_kernel(const float* __restrict__ unnormed,
                                  const float* __restrict__ gtd,
                                  const float* __restrict__ dis) {
    __shared__ float xbuf[N_];
    __shared__ float red[THREADS_];
    const int tid = threadIdx.x;
    const int blk = blockIdx.x;

    if (blk < B_) {
        for (int pass = 0; pass < 2; pass++) {
            const float* xin  = (pass == 0) ? unnormed + blk * N_ : gtd + blk * N_;
            float*       xout = (pass == 0) ? g_src + blk * N_    : g_tgt + blk * N_;
            for (int i = tid; i < N_; i += THREADS_) xbuf[i] = xin[i];
            __syncthreads();
            // softmax(-x): m = min(x); p_i = exp(m - x_i)/sum
            float m = 3.402823466e38f;
            for (int i = tid; i < N_; i += THREADS_) m = fminf(m, xbuf[i]);
            red[tid] = m;
            __syncthreads();
            for (int s = THREADS_ / 2; s > 0; s >>= 1) {
                if (tid < s) red[tid] = fminf(red[tid], red[tid + s]);
                __syncthreads();
            }
            m = red[0];
            __syncthreads();
            float sum = 0.f;
            for (int i = tid; i < N_; i += THREADS_) sum += expf(m - xbuf[i]);
            red[tid] = sum;
            __syncthreads();
            for (int s = THREADS_ / 2; s > 0; s >>= 1) {
                if (tid < s) red[tid] += red[tid + s];
                __syncthreads();
            }
            const float inv_tot = 1.0f / red[0];
            __syncthreads();
            for (int i = tid; i < N_; i += THREADS_) xout[i] = expf(m - xbuf[i]) * inv_tot;
            __syncthreads();
        }
    } else {
        // E[i,j] = dis[i, j*96] - dis[0,0]/2   (exact: dis[0,0] = 2*E[0,0])
        const float e00 = 0.5f * dis[0];
        for (int idx = tid; idx < D_ * D_; idx += THREADS_) {
            const int i = idx / D_, j = idx - i * D_;
            const float e = dis[(size_t)i * N_ + (size_t)j * D_] - e00;
            const float g = expf(e * (-0.1f));
            g_G [i * D_ + j] = g;
            g_GT[j * D_ + i] = g;
            g_HT[j * D_ + i] = e * g;
        }
    }
}

// ---------------- main: one CTA per batch ----------------
__global__ void __launch_bounds__(THREADS_, 1)
sinkhorn_kernel(const float* __restrict__ normed, const float* __restrict__ unnormed) {
    extern __shared__ float sm[];
    float* sG  = sm;                  // G[i][j]         (HT in epilogue)
    float* sGT = sm + 1 * D_ * STR_;  // G[j][i]
    float* sU  = sm + 2 * D_ * STR_;  // U[pa][pb]
    float* sV  = sm + 3 * D_ * STR_;  // V[jy][jx]
    float* sT  = sm + 4 * D_ * STR_;  // temp
    __shared__ float red[THREADS_ / 32];

    const int b   = blockIdx.x;
    const int tid = threadIdx.x;
    const int m0  = (tid >> 5) * 12;
    const int n0  = (tid & 31) * 3;
    const float eps = 1e-16f;

    for (int idx = tid; idx < D_ * D_; idx += THREADS_) {
        const int i = idx / D_, j = idx - i * D_;
        sG [i * STR_ + j] = g_G [idx];
        sGT[i * STR_ + j] = g_GT[idx];
        sU [i * STR_ + j] = 1.0f / 9216.0f;   // u0
    }
    __syncthreads();

    const float* __restrict__ srcb = g_src + b * N_;
    const float* __restrict__ tgtb = g_tgt + b * N_;

    unsigned long long acc[6][3];

    for (int it = 0; it < NITER_; it++) {
        // stage1: T[pb][jx] = sum_pa U[pa][pb] * G[pa][jx]
        gemm_core(sU, sG, m0, n0, acc);
        store_plain(sT, m0, n0, acc);
        __syncthreads();

        // stage2: S[jy][jx] = sum_pb G[pb][jy]*T[pb][jx];  V = src/(S+eps)
        gemm_core(sG, sT, m0, n0, acc);
#pragma unroll
        for (int t = 0; t < 6; t++)
#pragma unroll
            for (int j = 0; j < 3; j++) {
                float2 s = unpack2(acc[t][j]);
                const int r0 = m0 + 2 * t, c = n0 + j;
                sV[r0 * STR_ + c]       = __ldg(&srcb[r0 * D_ + c])       / (s.x + eps);
                sV[(r0 + 1) * STR_ + c] = __ldg(&srcb[(r0 + 1) * D_ + c]) / (s.y + eps);
            }
        __syncthreads();

        // stage3: W[jx][pb] = sum_jy V[jy][jx] * GT[jy][pb]
        gemm_core(sV, sGT, m0, n0, acc);
        store_plain(sT, m0, n0, acc);
        __syncthreads();

        // stage4: R[pa][pb] = sum_jx GT[jx][pa]*W[jx][pb];  U = tgt/(R+eps)
        gemm_core(sGT, sT, m0, n0, acc);
#pragma unroll
        for (int t = 0; t < 6; t++)
#pragma unroll
            for (int j = 0; j < 3; j++) {
                float2 s = unpack2(acc[t][j]);
                const int r0 = m0 + 2 * t, c = n0 + j;
                sU[r0 * STR_ + c]       = __ldg(&tgtb[r0 * D_ + c])       / (s.x + eps);
                sU[(r0 + 1) * STR_ + c] = __ldg(&tgtb[(r0 + 1) * D_ + c]) / (s.y + eps);
            }
        __syncthreads();
    }
    // Final state: sU = u, sV = v, sT = W(final v).

    // beta / ot / loss accumulation (reads sV and gmem only)
    float ot_acc = 0.f, loss_acc = 0.f;
    {
        const float* __restrict__ nb = normed + b * N_;
        const float* __restrict__ ub = unnormed + b * N_;
        for (int q = tid; q < N_; q += THREADS_) {
            const int jy = q / D_, jx = q - jy * D_;
            const float v    = sV[jy * STR_ + jx];
            const float beta = 10.0f * logf(v + eps);
            ot_acc += __ldg(&nb[q]) * beta;
            const float s = __ldg(&srcb[q]);
            loss_acc += __ldg(&ub[q]) * (-s * (1.0f + s) * beta);
        }
    }

    // wd = sum U .* (R1 + R2),  M = H(x)G + G(x)H, H = E.*G
    // Load HT into sG (G no longer needed).
    for (int idx = tid; idx < D_ * D_; idx += THREADS_) {
        const int i = idx / D_, j = idx - i * D_;
        sG[i * STR_ + j] = g_HT[idx];
    }
    __syncthreads();

    // R2[pa][pb] = sum_jx HT[jx][pa] * W[jx][pb]
    gemm_core(sG, sT, m0, n0, acc);
    float wd_acc = dot_tile(acc, sU, m0, n0);
    __syncthreads();   // before overwriting sT

    // W2[jx][pb] = sum_jy V[jy][jx] * HT[jy][pb]
    gemm_core(sV, sG, m0, n0, acc);
    store_plain(sT, m0, n0, acc);
    __syncthreads();

    // R1[pa][pb] = sum_jx GT[jx][pa] * W2[jx][pb]
    gemm_core(sGT, sT, m0, n0, acc);
    wd_acc += dot_tile(acc, sU, m0, n0);

    const float L  = block_sum(loss_acc, red);
    const float WD = block_sum(wd_acc, red);
    const float OT = block_sum(ot_acc, red);
    if (tid == 0) {
        g_partial[b][0] = L;
        g_partial[b][1] = WD;
        g_partial[b][2] = OT;
    }
}

__global__ void finalize_kernel(float* __restrict__ out) {
    const int t = threadIdx.x;
    if (t < 3) {
        float s = 0.f;
#pragma unroll
        for (int i = 0; i < B_; i++) s += g_partial[i][t];
        out[t] = s;   // (loss, wd, ot_obj)
    }
}

extern "C" void kernel_launch(void* const* d_in, const int* in_sizes, int n_in,
                              void* d_out, int out_size) {
    const float* normed   = (const float*)d_in[0];
    const float* unnormed = (const float*)d_in[1];
    const float* gtd      = (const float*)d_in[2];
    const float* dis      = (const float*)d_in[3];
    // d_in[4] = points (int64), unused by the reference computation.

    cudaFuncSetAttribute(sinkhorn_kernel,
                         cudaFuncAttributeMaxDynamicSharedMemorySize, SMEM_BYTES_);

    precompute_kernel<<<B_ + 1, THREADS_>>>(unnormed, gtd, dis);
    sinkhorn_kernel<<<B_, THREADS_, SMEM_BYTES_>>>(normed, unnormed);
    finalize_kernel<<<1, 32>>>((float*)d_out);
}

// round 11
// speedup vs baseline: 1.2210x; 1.2210x over previous
#include <cuda_runtime.h>

// OT_Loss (Sinkhorn, N=9216, B=8, 100 iters) via separable-kernel factorization.
// dis[p,q] = E[pb,jy] + E[pa,jx]  =>  K = G (x) G with G = exp(-E/10), E 96x96.
// Each N x N matvec = two 96x96x96 fp32 GEMMs. One CTA per batch, all-SMEM.
// R10: stride 98->100, a-loads as LDS.128 (halves LDS wavefronts), src/tgt
//      tiles hoisted into registers.

#define D_        96
#define N_        9216
#define B_        8
#define NITER_    100
#define STR_      100
#define THREADS_  256
#define PTHREADS_ 1024
#define SMEM_BYTES_ (5 * D_ * STR_ * sizeof(float))   // 192000 B

__device__ float g_G  [D_ * D_];    // G[i][j]
__device__ float g_GT [D_ * D_];    // G[j][i]
__device__ float g_HT [D_ * D_];    // H^T: g_HT[j][i] = (E*G)[i][j]
__device__ float g_src[B_ * N_];    // softmax(-unnormed)  (= b)
__device__ float g_tgt[B_ * N_];    // softmax(-gt)        (= a)
__device__ float g_partial[B_][3];  // per-batch (loss, wd, ot)

// ---------------- f32x2 helpers ----------------
__device__ __forceinline__ unsigned long long dup2(float x) {
    unsigned long long d;
    asm("mov.b64 %0, {%1, %1};" : "=l"(d) : "f"(x));
    return d;
}
__device__ __forceinline__ unsigned long long fma2(unsigned long long a,
                                                   unsigned long long b,
                                                   unsigned long long c) {
    unsigned long long d;
    asm("fma.rn.f32x2 %0, %1, %2, %3;" : "=l"(d) : "l"(a), "l"(b), "l"(c));
    return d;
}
__device__ __forceinline__ float2 unpack2(unsigned long long v) {
    float2 r;
    asm("mov.b64 {%0, %1}, %2;" : "=f"(r.x), "=f"(r.y) : "l"(v));
    return r;
}

// ---------------- 96x96x96 TN GEMM: C[m,n] = sum_k A[k][m]*B[k][n] -----------
// Thread tile: 12 m-rows (6 f32x2 pairs, 3x LDS.128) x 3 n-cols.
// warp -> m0 = 12*warp (16B aligned: 48*warp bytes), lane -> n0 = 3*lane.
__device__ __forceinline__ void gemm_core(const float* __restrict__ A,
                                          const float* __restrict__ Bm,
                                          int m0, int n0,
                                          unsigned long long acc[6][3]) {
#pragma unroll
    for (int t = 0; t < 6; t++)
#pragma unroll
        for (int j = 0; j < 3; j++) acc[t][j] = 0ULL;

    const float* ap = A + m0;   // 16B aligned (m0 mult of 12 -> 48B; STR_*4=400B)
    const float* bp = Bm + n0;  // conflict-free: bank (4k + 3*lane) mod 32 bijective
#pragma unroll 2
    for (int k = 0; k < D_; k++) {
        ulonglong2 a01 = *reinterpret_cast<const ulonglong2*>(ap);
        ulonglong2 a23 = *reinterpret_cast<const ulonglong2*>(ap + 4);
        ulonglong2 a45 = *reinterpret_cast<const ulonglong2*>(ap + 8);
        unsigned long long a[6] = {a01.x, a01.y, a23.x, a23.y, a45.x, a45.y};
        unsigned long long b0 = dup2(bp[0]);
        unsigned long long b1 = dup2(bp[1]);
        unsigned long long b2 = dup2(bp[2]);
#pragma unroll
        for (int t = 0; t < 6; t++) {
            acc[t][0] = fma2(a[t], b0, acc[t][0]);
            acc[t][1] = fma2(a[t], b1, acc[t][1]);
            acc[t][2] = fma2(a[t], b2, acc[t][2]);
        }
        ap += STR_;
        bp += STR_;
    }
}

__device__ __forceinline__ void store_plain(float* __restrict__ C, int m0, int n0,
                                            unsigned long long acc[6][3]) {
#pragma unroll
    for (int t = 0; t < 6; t++)
#pragma unroll
        for (int j = 0; j < 3; j++) {
            float2 v = unpack2(acc[t][j]);
            C[(m0 + 2 * t)     * STR_ + n0 + j] = v.x;
            C[(m0 + 2 * t + 1) * STR_ + n0 + j] = v.y;
        }
}

__device__ __forceinline__ float dot_tile(unsigned long long acc[6][3],
                                          const float* __restrict__ Um,
                                          int m0, int n0) {
    float s = 0.f;
#pragma unroll
    for (int t = 0; t < 6; t++)
#pragma unroll
        for (int j = 0; j < 3; j++) {
            float2 v = unpack2(acc[t][j]);
            s += v.x * Um[(m0 + 2 * t)     * STR_ + n0 + j];
            s += v.y * Um[(m0 + 2 * t + 1) * STR_ + n0 + j];
        }
    return s;
}

__device__ __forceinline__ float block_sum(float v, float* red) {
#pragma unroll
    for (int o = 16; o > 0; o >>= 1) v += __shfl_down_sync(0xffffffffu, v, o);
    __syncthreads();
    if ((threadIdx.x & 31) == 0) red[threadIdx.x >> 5] = v;
    __syncthreads();
    if (threadIdx.x == 0) {
        float s = 0.f;
#pragma unroll
        for (int i = 0; i < THREADS_ / 32; i++) s += red[i];
        v = s;
    }
    return v;  // valid on tid 0 only
}

// ---------------- precompute: softmaxes + G / G^T / H^T ----------------
__global__ void __launch_bounds__(PTHREADS_)
precompute_kernel(const float* __restrict__ unnormed,
                  const float* __restrict__ gtd,
                  const float* __restrict__ dis) {
    __shared__ float xbuf[N_];
    __shared__ float red[PTHREADS_];
    const int tid = threadIdx.x;
    const int blk = blockIdx.x;

    if (blk < B_) {
        for (int pass = 0; pass < 2; pass++) {
            const float* xin  = (pass == 0) ? unnormed + blk * N_ : gtd + blk * N_;
            float*       xout = (pass == 0) ? g_src + blk * N_    : g_tgt + blk * N_;
            for (int i = tid; i < N_; i += PTHREADS_) xbuf[i] = xin[i];
            __syncthreads();
            // softmax(-x): m = min(x); p_i = exp(m - x_i)/sum
            float m = 3.402823466e38f;
            for (int i = tid; i < N_; i += PTHREADS_) m = fminf(m, xbuf[i]);
            red[tid] = m;
            __syncthreads();
            for (int s = PTHREADS_ / 2; s > 0; s >>= 1) {
                if (tid < s) red[tid] = fminf(red[tid], red[tid + s]);
                __syncthreads();
            }
            m = red[0];
            __syncthreads();
            float sum = 0.f;
            for (int i = tid; i < N_; i += PTHREADS_) sum += expf(m - xbuf[i]);
            red[tid] = sum;
            __syncthreads();
            for (int s = PTHREADS_ / 2; s > 0; s >>= 1) {
                if (tid < s) red[tid] += red[tid + s];
                __syncthreads();
            }
            const float inv_tot = 1.0f / red[0];
            __syncthreads();
            for (int i = tid; i < N_; i += PTHREADS_) xout[i] = expf(m - xbuf[i]) * inv_tot;
            __syncthreads();
        }
    } else {
        // E[i,j] = dis[i, j*96] - dis[0,0]/2   (exact: dis[0,0] = 2*E[0,0])
        const float e00 = 0.5f * dis[0];
        for (int idx = tid; idx < D_ * D_; idx += PTHREADS_) {
            const int i = idx / D_, j = idx - i * D_;
            const float e = dis[(size_t)i * N_ + (size_t)j * D_] - e00;
            const float g = expf(e * (-0.1f));
            g_G [i * D_ + j] = g;
            g_GT[j * D_ + i] = g;
            g_HT[j * D_ + i] = e * g;
        }
    }
}

// ---------------- main: one CTA per batch ----------------
__global__ void __launch_bounds__(THREADS_, 1)
sinkhorn_kernel(const float* __restrict__ normed, const float* __restrict__ unnormed) {
    extern __shared__ float sm[];
    float* sG  = sm;                  // G[i][j]         (HT in epilogue)
    float* sGT = sm + 1 * D_ * STR_;  // G[j][i]
    float* sU  = sm + 2 * D_ * STR_;  // U[pa][pb]
    float* sV  = sm + 3 * D_ * STR_;  // V[jy][jx]
    float* sT  = sm + 4 * D_ * STR_;  // temp
    __shared__ float red[THREADS_ / 32];

    const int b   = blockIdx.x;
    const int tid = threadIdx.x;
    const int m0  = (tid >> 5) * 12;
    const int n0  = (tid & 31) * 3;
    const float eps = 1e-16f;

    for (int idx = tid; idx < D_ * D_; idx += THREADS_) {
        const int i = idx / D_, j = idx - i * D_;
        sG [i * STR_ + j] = g_G [idx];
        sGT[i * STR_ + j] = g_GT[idx];
        sU [i * STR_ + j] = 1.0f / 9216.0f;   // u0
    }
    __syncthreads();

    const float* __restrict__ srcb = g_src + b * N_;
    const float* __restrict__ tgtb = g_tgt + b * N_;

    // Hoist the per-thread src/tgt tiles (iteration-invariant) into registers.
    float psrc[12][3], ptgt[12][3];
#pragma unroll
    for (int i = 0; i < 12; i++)
#pragma unroll
        for (int j = 0; j < 3; j++) {
            psrc[i][j] = __ldg(&srcb[(m0 + i) * D_ + n0 + j]);
            ptgt[i][j] = __ldg(&tgtb[(m0 + i) * D_ + n0 + j]);
        }

    unsigned long long acc[6][3];

    for (int it = 0; it < NITER_; it++) {
        // stage1: T[pb][jx] = sum_pa U[pa][pb] * G[pa][jx]
        gemm_core(sU, sG, m0, n0, acc);
        store_plain(sT, m0, n0, acc);
        __syncthreads();

        // stage2: S[jy][jx] = sum_pb G[pb][jy]*T[pb][jx];  V = src/(S+eps)
        gemm_core(sG, sT, m0, n0, acc);
#pragma unroll
        for (int t = 0; t < 6; t++)
#pragma unroll
            for (int j = 0; j < 3; j++) {
                float2 s = unpack2(acc[t][j]);
                const int r0 = m0 + 2 * t, c = n0 + j;
                sV[r0 * STR_ + c]       = psrc[2 * t][j]     / (s.x + eps);
                sV[(r0 + 1) * STR_ + c] = psrc[2 * t + 1][j] / (s.y + eps);
            }
        __syncthreads();

        // stage3: W[jx][pb] = sum_jy V[jy][jx] * GT[jy][pb]
        gemm_core(sV, sGT, m0, n0, acc);
        store_plain(sT, m0, n0, acc);
        __syncthreads();

        // stage4: R[pa][pb] = sum_jx GT[jx][pa]*W[jx][pb];  U = tgt/(R+eps)
        gemm_core(sGT, sT, m0, n0, acc);
#pragma unroll
        for (int t = 0; t < 6; t++)
#pragma unroll
            for (int j = 0; j < 3; j++) {
                float2 s = unpack2(acc[t][j]);
                const int r0 = m0 + 2 * t, c = n0 + j;
                sU[r0 * STR_ + c]       = ptgt[2 * t][j]     / (s.x + eps);
                sU[(r0 + 1) * STR_ + c] = ptgt[2 * t + 1][j] / (s.y + eps);
            }
        __syncthreads();
    }
    // Final state: sU = u, sV = v, sT = W(final v).

    // beta / ot / loss accumulation (reads sV and gmem only)
    float ot_acc = 0.f, loss_acc = 0.f;
    {
        const float* __restrict__ nb = normed + b * N_;
        const float* __restrict__ ub = unnormed + b * N_;
        for (int q = tid; q < N_; q += THREADS_) {
            const int jy = q / D_, jx = q - jy * D_;
            const float v    = sV[jy * STR_ + jx];
            const float beta = 10.0f * logf(v + eps);
            ot_acc += __ldg(&nb[q]) * beta;
            const float s = __ldg(&srcb[q]);
            loss_acc += __ldg(&ub[q]) * (-s * (1.0f + s) * beta);
        }
    }

    // wd = sum U .* (R1 + R2),  M = H(x)G + G(x)H, H = E.*G
    // Load HT into sG (G no longer needed).
    for (int idx = tid; idx < D_ * D_; idx += THREADS_) {
        const int i = idx / D_, j = idx - i * D_;
        sG[i * STR_ + j] = g_HT[idx];
    }
    __syncthreads();

    // R2[pa][pb] = sum_jx HT[jx][pa] * W[jx][pb]
    gemm_core(sG, sT, m0, n0, acc);
    float wd_acc = dot_tile(acc, sU, m0, n0);
    __syncthreads();   // before overwriting sT

    // W2[jx][pb] = sum_jy V[jy][jx] * HT[jy][pb]
    gemm_core(sV, sG, m0, n0, acc);
    store_plain(sT, m0, n0, acc);
    __syncthreads();

    // R1[pa][pb] = sum_jx GT[jx][pa] * W2[jx][pb]
    gemm_core(sGT, sT, m0, n0, acc);
    wd_acc += dot_tile(acc, sU, m0, n0);

    const float L  = block_sum(loss_acc, red);
    const float WD = block_sum(wd_acc, red);
    const float OT = block_sum(ot_acc, red);
    if (tid == 0) {
        g_partial[b][0] = L;
        g_partial[b][1] = WD;
        g_partial[b][2] = OT;
    }
}

__global__ void finalize_kernel(float* __restrict__ out) {
    const int t = threadIdx.x;
    if (t < 3) {
        float s = 0.f;
#pragma unroll
        for (int i = 0; i < B_; i++) s += g_partial[i][t];
        out[t] = s;   // (loss, wd, ot_obj)
    }
}

extern "C" void kernel_launch(void* const* d_in, const int* in_sizes, int n_in,
                              void* d_out, int out_size) {
    const float* normed   = (const float*)d_in[0];
    const float* unnormed = (const float*)d_in[1];
    const float* gtd      = (const float*)d_in[2];
    const float* dis      = (const float*)d_in[3];
    // d_in[4] = points (int64), unused by the reference computation.

    cudaFuncSetAttribute(sinkhorn_kernel,
                         cudaFuncAttributeMaxDynamicSharedMemorySize, SMEM_BYTES_);

    precompute_kernel<<<B_ + 1, PTHREADS_>>>(unnormed, gtd, dis);
    sinkhorn_kernel<<<B_, THREADS_, SMEM_BYTES_>>>(normed, unnormed);
    finalize_kernel<<<1, 32>>>((float*)d_out);
}

// round 12
// speedup vs baseline: 1.7045x; 1.3960x over previous
#include <cuda_runtime.h>
#include <cstdint>

// OT_Loss (Sinkhorn, N=9216, B=8, 100 iters), separable kernel K = G (x) G.
// R11: 2-CTA cluster per batch, jx-column split. Only stage4's partial-R needs
// a cross-CTA exchange (36KB DSMEM + 2 cluster syncs per iteration).
// All GEMM inner loops use k+1 register prefetch + fma.rn.f32x2.

#define D_        96
#define N_        9216
#define B_        8
#define NITER_    100
#define STR_      100                 // stride for 96-wide matrices
#define SVT_      52                  // stride for 48-wide matrices
#define THREADS_  256
#define PTHREADS_ 1024

// SMEM layout (floats)
#define OFF_G_   0
#define OFF_GT_  9600
#define OFF_U_   19200
#define OFF_RP_  28800                // peer-incoming partial R
#define OFF_V_   38400                // 96 x 48 (stride 52)
#define OFF_T_   43392                // 96 x 48 (stride 52)
#define OFF_W_   48384                // 48 x 96 (stride 100)
#define SMEM_FLOATS_ 53184
#define SMEM_BYTES_  (SMEM_FLOATS_ * sizeof(float))   // 212736 B

__device__ float g_G  [D_ * D_];
__device__ float g_GT [D_ * D_];
__device__ float g_HT [D_ * D_];      // (E*G)^T
__device__ float g_src[B_ * N_];
__device__ float g_tgt[B_ * N_];
__device__ float g_partial[2 * B_][3];

typedef unsigned long long ull;

// ---------------- f32x2 / PTX helpers ----------------
__device__ __forceinline__ ull dup2(float x) {
    ull d; asm("mov.b64 %0, {%1, %1};" : "=l"(d) : "f"(x)); return d;
}
__device__ __forceinline__ ull fma2(ull a, ull b, ull c) {
    ull d; asm("fma.rn.f32x2 %0, %1, %2, %3;" : "=l"(d) : "l"(a), "l"(b), "l"(c));
    return d;
}
__device__ __forceinline__ float2 unpack2(ull v) {
    float2 r; asm("mov.b64 {%0, %1}, %2;" : "=f"(r.x), "=f"(r.y) : "l"(v)); return r;
}
__device__ __forceinline__ ull ld2(const float* p) {
    return *reinterpret_cast<const ull*>(p);
}
__device__ __forceinline__ uint32_t smem_u32(const void* p) {
    uint32_t a;
    asm("{ .reg .u64 t; cvta.to.shared.u64 t, %1; cvt.u32.u64 %0, t; }"
        : "=r"(a) : "l"(p));
    return a;
}
__device__ __forceinline__ uint32_t mapa_peer(uint32_t addr, uint32_t rank) {
    uint32_t r;
    asm("mapa.shared::cluster.u32 %0, %1, %2;" : "=r"(r) : "r"(addr), "r"(rank));
    return r;
}
__device__ __forceinline__ void st_cluster_f32(uint32_t addr, float v) {
    asm volatile("st.shared::cluster.f32 [%0], %1;" :: "r"(addr), "f"(v) : "memory");
}
__device__ __forceinline__ void cluster_sync() {
    asm volatile("barrier.cluster.arrive.aligned;" ::: "memory");
    asm volatile("barrier.cluster.wait.aligned;" ::: "memory");
}
__device__ __forceinline__ uint32_t ctarank() {
    uint32_t r; asm("mov.u32 %0, %%cluster_ctarank;" : "=r"(r)); return r;
}

// ---------------- GEMM cores: C[m,n] = sum_k A[k][m] * B[k][n] --------------
// 6x3 tile (3 f32x2 pairs x 3 cols), k+1 prefetch.
template <int K, int LDA, int LDB>
__device__ __forceinline__ void gemm6x3(const float* __restrict__ A,
                                        const float* __restrict__ Bm,
                                        int m0, int n0, ull acc[3][3]) {
#pragma unroll
    for (int t = 0; t < 3; t++)
#pragma unroll
        for (int j = 0; j < 3; j++) acc[t][j] = 0ULL;

    const float* ap = A + m0;
    const float* bp = Bm + n0;
    ull a0 = ld2(ap), a1 = ld2(ap + 2), a2 = ld2(ap + 4);
    float b0 = bp[0], b1 = bp[1], b2 = bp[2];
#pragma unroll 4
    for (int k = 0; k < K - 1; k++) {
        ap += LDA; bp += LDB;
        ull na0 = ld2(ap), na1 = ld2(ap + 2), na2 = ld2(ap + 4);
        float nb0 = bp[0], nb1 = bp[1], nb2 = bp[2];
        ull B0 = dup2(b0), B1 = dup2(b1), B2 = dup2(b2);
        acc[0][0] = fma2(a0, B0, acc[0][0]);
        acc[0][1] = fma2(a0, B1, acc[0][1]);
        acc[0][2] = fma2(a0, B2, acc[0][2]);
        acc[1][0] = fma2(a1, B0, acc[1][0]);
        acc[1][1] = fma2(a1, B1, acc[1][1]);
        acc[1][2] = fma2(a1, B2, acc[1][2]);
        acc[2][0] = fma2(a2, B0, acc[2][0]);
        acc[2][1] = fma2(a2, B1, acc[2][1]);
        acc[2][2] = fma2(a2, B2, acc[2][2]);
        a0 = na0; a1 = na1; a2 = na2; b0 = nb0; b1 = nb1; b2 = nb2;
    }
    ull B0 = dup2(b0), B1 = dup2(b1), B2 = dup2(b2);
    acc[0][0] = fma2(a0, B0, acc[0][0]);
    acc[0][1] = fma2(a0, B1, acc[0][1]);
    acc[0][2] = fma2(a0, B2, acc[0][2]);
    acc[1][0] = fma2(a1, B0, acc[1][0]);
    acc[1][1] = fma2(a1, B1, acc[1][1]);
    acc[1][2] = fma2(a1, B2, acc[1][2]);
    acc[2][0] = fma2(a2, B0, acc[2][0]);
    acc[2][1] = fma2(a2, B1, acc[2][1]);
    acc[2][2] = fma2(a2, B2, acc[2][2]);
}

// 12x3 tile (6 f32x2 pairs via LDS.128), k+1 prefetch.
template <int K, int LDA, int LDB>
__device__ __forceinline__ void gemm12x3(const float* __restrict__ A,
                                         const float* __restrict__ Bm,
                                         int m0, int n0, ull acc[6][3]) {
#pragma unroll
    for (int t = 0; t < 6; t++)
#pragma unroll
        for (int j = 0; j < 3; j++) acc[t][j] = 0ULL;

    const float* ap = A + m0;   // 16B aligned (m0 multiple of 12)
    const float* bp = Bm + n0;
    ulonglong2 p0 = *reinterpret_cast<const ulonglong2*>(ap);
    ulonglong2 p1 = *reinterpret_cast<const ulonglong2*>(ap + 4);
    ulonglong2 p2 = *reinterpret_cast<const ulonglong2*>(ap + 8);
    float b0 = bp[0], b1 = bp[1], b2 = bp[2];
#pragma unroll 4
    for (int k = 0; k < K - 1; k++) {
        ap += LDA; bp += LDB;
        ulonglong2 q0 = *reinterpret_cast<const ulonglong2*>(ap);
        ulonglong2 q1 = *reinterpret_cast<const ulonglong2*>(ap + 4);
        ulonglong2 q2 = *reinterpret_cast<const ulonglong2*>(ap + 8);
        float nb0 = bp[0], nb1 = bp[1], nb2 = bp[2];
        ull B0 = dup2(b0), B1 = dup2(b1), B2 = dup2(b2);
        ull a[6] = {p0.x, p0.y, p1.x, p1.y, p2.x, p2.y};
#pragma unroll
        for (int t = 0; t < 6; t++) {
            acc[t][0] = fma2(a[t], B0, acc[t][0]);
            acc[t][1] = fma2(a[t], B1, acc[t][1]);
            acc[t][2] = fma2(a[t], B2, acc[t][2]);
        }
        p0 = q0; p1 = q1; p2 = q2; b0 = nb0; b1 = nb1; b2 = nb2;
    }
    ull B0 = dup2(b0), B1 = dup2(b1), B2 = dup2(b2);
    ull a[6] = {p0.x, p0.y, p1.x, p1.y, p2.x, p2.y};
#pragma unroll
    for (int t = 0; t < 6; t++) {
        acc[t][0] = fma2(a[t], B0, acc[t][0]);
        acc[t][1] = fma2(a[t], B1, acc[t][1]);
        acc[t][2] = fma2(a[t], B2, acc[t][2]);
    }
}

__device__ __forceinline__ void store6x3(float* __restrict__ C, int ldc,
                                         int m0, int n0, ull acc[3][3]) {
#pragma unroll
    for (int t = 0; t < 3; t++)
#pragma unroll
        for (int j = 0; j < 3; j++) {
            float2 v = unpack2(acc[t][j]);
            C[(m0 + 2 * t)     * ldc + n0 + j] = v.x;
            C[(m0 + 2 * t + 1) * ldc + n0 + j] = v.y;
        }
}

__device__ __forceinline__ float dot12x3(ull acc[6][3],
                                         const float* __restrict__ Um,
                                         int m0, int n0) {
    float s = 0.f;
#pragma unroll
    for (int t = 0; t < 6; t++)
#pragma unroll
        for (int j = 0; j < 3; j++) {
            float2 v = unpack2(acc[t][j]);
            s += v.x * Um[(m0 + 2 * t)     * STR_ + n0 + j];
            s += v.y * Um[(m0 + 2 * t + 1) * STR_ + n0 + j];
        }
    return s;
}

__device__ __forceinline__ float block_sum(float v, float* red) {
#pragma unroll
    for (int o = 16; o > 0; o >>= 1) v += __shfl_down_sync(0xffffffffu, v, o);
    __syncthreads();
    if ((threadIdx.x & 31) == 0) red[threadIdx.x >> 5] = v;
    __syncthreads();
    if (threadIdx.x == 0) {
        float s = 0.f;
#pragma unroll
        for (int i = 0; i < THREADS_ / 32; i++) s += red[i];
        v = s;
    }
    return v;  // valid on tid 0
}

// ---------------- precompute (unchanged from R10) ----------------
__global__ void __launch_bounds__(PTHREADS_)
precompute_kernel(const float* __restrict__ unnormed,
                  const float* __restrict__ gtd,
                  const float* __restrict__ dis) {
    __shared__ float xbuf[N_];
    __shared__ float red[PTHREADS_];
    const int tid = threadIdx.x;
    const int blk = blockIdx.x;

    if (blk < B_) {
        for (int pass = 0; pass < 2; pass++) {
            const float* xin  = (pass == 0) ? unnormed + blk * N_ : gtd + blk * N_;
            float*       xout = (pass == 0) ? g_src + blk * N_    : g_tgt + blk * N_;
            for (int i = tid; i < N_; i += PTHREADS_) xbuf[i] = xin[i];
            __syncthreads();
            float m = 3.402823466e38f;
            for (int i = tid; i < N_; i += PTHREADS_) m = fminf(m, xbuf[i]);
            red[tid] = m;
            __syncthreads();
            for (int s = PTHREADS_ / 2; s > 0; s >>= 1) {
                if (tid < s) red[tid] = fminf(red[tid], red[tid + s]);
                __syncthreads();
            }
            m = red[0];
            __syncthreads();
            float sum = 0.f;
            for (int i = tid; i < N_; i += PTHREADS_) sum += expf(m - xbuf[i]);
            red[tid] = sum;
            __syncthreads();
            for (int s = PTHREADS_ / 2; s > 0; s >>= 1) {
                if (tid < s) red[tid] += red[tid + s];
                __syncthreads();
            }
            const float inv_tot = 1.0f / red[0];
            __syncthreads();
            for (int i = tid; i < N_; i += PTHREADS_) xout[i] = expf(m - xbuf[i]) * inv_tot;
            __syncthreads();
        }
    } else {
        const float e00 = 0.5f * dis[0];
        for (int idx = tid; idx < D_ * D_; idx += PTHREADS_) {
            const int i = idx / D_, j = idx - i * D_;
            const float e = dis[(size_t)i * N_ + (size_t)j * D_] - e00;
            const float g = expf(e * (-0.1f));
            g_G [i * D_ + j] = g;
            g_GT[j * D_ + i] = g;
            g_HT[j * D_ + i] = e * g;
        }
    }
}

// ---------------- main: 2-CTA cluster per batch ----------------
__global__ void __launch_bounds__(THREADS_, 1) __cluster_dims__(2, 1, 1)
sinkhorn_kernel(const float* __restrict__ normed, const float* __restrict__ unnormed) {
    extern __shared__ float sm[];
    float* sG  = sm + OFF_G_;    // G (HT in epilogue)
    float* sGT = sm + OFF_GT_;
    float* sU  = sm + OFF_U_;    // full U (replicated)
    float* sRp = sm + OFF_RP_;   // peer-incoming partial R
    float* sV  = sm + OFF_V_;    // own-half V  [jy][jxl], stride 52
    float* sT  = sm + OFF_T_;    // own-half T  [pb][jxl], stride 52
    float* sW  = sm + OFF_W_;    // own-half W  [jxl][pb], stride 100
    __shared__ float red[THREADS_ / 32];

    const int      tid  = threadIdx.x;
    const uint32_t rank = ctarank();
    const int      b    = blockIdx.x >> 1;
    const int      jxo  = (int)rank * 48;
    const int      lane = tid & 31;
    const int      w    = tid >> 5;

    // tile maps
    const int mA0 = w * 12 + (lane >> 4) * 6;   // 96-m half-split map
    const int nA0 = (lane & 15) * 3;            // 48-n local
    const int mB0 = w * 6;                      // 48-m map
    const int nB0 = lane * 3;                   // 96-n
    const int mC0 = w * 12;                     // 96-m full map
    const int nC0 = lane * 3;                   // 96-n
    const float eps = 1e-16f;

    for (int idx = tid; idx < D_ * D_; idx += THREADS_) {
        const int i = idx / D_, j = idx - i * D_;
        sG [i * STR_ + j] = g_G [idx];
        sGT[i * STR_ + j] = g_GT[idx];
        sU [i * STR_ + j] = 1.0f / 9216.0f;
    }
    __syncthreads();

    const float* __restrict__ srcb = g_src + b * N_;
    const float* __restrict__ tgtb = g_tgt + b * N_;

    // hoisted iteration-invariant tiles
    float psrc[6][3];    // stage2 epilogue tile (map A, cols jxo+nA0)
    float ptgt[12][3];   // stage4 epilogue tile (map C)
#pragma unroll
    for (int i = 0; i < 6; i++)
#pragma unroll
        for (int j = 0; j < 3; j++)
            psrc[i][j] = __ldg(&srcb[(mA0 + i) * D_ + jxo + nA0 + j]);
#pragma unroll
    for (int i = 0; i < 12; i++)
#pragma unroll
        for (int j = 0; j < 3; j++)
            ptgt[i][j] = __ldg(&tgtb[(mC0 + i) * D_ + nC0 + j]);

    const uint32_t rp_local = smem_u32(sRp);
    const uint32_t rp_peer  = mapa_peer(rp_local, rank ^ 1u);

    ull acc3[3][3];
    ull acc6[6][3];

    for (int it = 0; it < NITER_; it++) {
        // stage1: T[pb][jxl] = sum_pa U[pa][pb] * G[pa][jxo+jxl]
        gemm6x3<D_, STR_, STR_>(sU, sG + jxo, mA0, nA0, acc3);
        store6x3(sT, SVT_, mA0, nA0, acc3);
        __syncthreads();

        // stage2: S[jy][jxl] = sum_pb G[pb][jy] * T[pb][jxl];  V = src/(S+eps)
        gemm6x3<D_, STR_, SVT_>(sG, sT, mA0, nA0, acc3);
#pragma unroll
        for (int t = 0; t < 3; t++)
#pragma unroll
            for (int j = 0; j < 3; j++) {
                float2 s = unpack2(acc3[t][j]);
                const int r0 = mA0 + 2 * t, c = nA0 + j;
                sV[r0 * SVT_ + c]       = psrc[2 * t][j]     / (s.x + eps);
                sV[(r0 + 1) * SVT_ + c] = psrc[2 * t + 1][j] / (s.y + eps);
            }
        __syncthreads();

        // stage3: W[jxl][pb] = sum_jy V[jy][jxl] * GT[jy][pb]
        gemm6x3<D_, SVT_, STR_>(sV, sGT, mB0, nB0, acc3);
        store6x3(sW, STR_, mB0, nB0, acc3);
        __syncthreads();

        // stage4 (partial): Rr[pa][pb] = sum_{jxl} GT[jxo+jxl][pa] * W[jxl][pb]
        gemm12x3<48, STR_, STR_>(sGT + (size_t)jxo * STR_, sW, mC0, nC0, acc6);

        // exchange: send own partial tile to peer's sRp
        cluster_sync();   // peer finished reading sRp from previous iteration
#pragma unroll
        for (int t = 0; t < 6; t++)
#pragma unroll
            for (int j = 0; j < 3; j++) {
                float2 v = unpack2(acc6[t][j]);
                st_cluster_f32(rp_peer + 4u * ((mC0 + 2 * t)     * STR_ + nC0 + j), v.x);
                st_cluster_f32(rp_peer + 4u * ((mC0 + 2 * t + 1) * STR_ + nC0 + j), v.y);
            }
        cluster_sync();   // peer's partial visible in sRp

        // U = tgt / (own partial + peer partial + eps)
#pragma unroll
        for (int t = 0; t < 6; t++)
#pragma unroll
            for (int j = 0; j < 3; j++) {
                float2 v = unpack2(acc6[t][j]);
                const int r0 = mC0 + 2 * t, c = nC0 + j;
                sU[r0 * STR_ + c]       = ptgt[2 * t][j]     / (v.x + sRp[r0 * STR_ + c] + eps);
                sU[(r0 + 1) * STR_ + c] = ptgt[2 * t + 1][j] / (v.y + sRp[(r0 + 1) * STR_ + c] + eps);
            }
        __syncthreads();
    }
    // Final: sU = u (full), sV = v (own half), sW = W(final v, own half).

    // ot / loss partials over own jx half
    float ot_acc = 0.f, loss_acc = 0.f;
    {
        const float* __restrict__ nb = normed + b * N_;
        const float* __restrict__ ub = unnormed + b * N_;
        for (int idx = tid; idx < D_ * 48; idx += THREADS_) {
            const int jy = idx / 48, jxl = idx - jy * 48;
            const int q = jy * D_ + jxo + jxl;
            const float v    = sV[jy * SVT_ + jxl];
            const float beta = 10.0f * logf(v + eps);
            ot_acc += __ldg(&nb[q]) * beta;
            const float s = __ldg(&srcb[q]);
            loss_acc += __ldg(&ub[q]) * (-s * (1.0f + s) * beta);
        }
    }

    // wd partials: M = H(x)G + G(x)H, H = E.*G.  Load HT over sG.
    for (int idx = tid; idx < D_ * D_; idx += THREADS_) {
        const int i = idx / D_, j = idx - i * D_;
        sG[i * STR_ + j] = g_HT[idx];
    }
    __syncthreads();

    // R2 partial: sum_{jxl} HT[jxo+jxl][pa] * W[jxl][pb]
    gemm12x3<48, STR_, STR_>(sG + (size_t)jxo * STR_, sW, mC0, nC0, acc6);
    float wd_acc = dot12x3(acc6, sU, mC0, nC0);
    __syncthreads();   // before overwriting sW

    // W2[jxl][pb] = sum_jy V[jy][jxl] * HT[jy][pb]
    gemm6x3<D_, SVT_, STR_>(sV, sG, mB0, nB0, acc3);
    store6x3(sW, STR_, mB0, nB0, acc3);
    __syncthreads();

    // R1 partial: sum_{jxl} GT[jxo+jxl][pa] * W2[jxl][pb]
    gemm12x3<48, STR_, STR_>(sGT + (size_t)jxo * STR_, sW, mC0, nC0, acc6);
    wd_acc += dot12x3(acc6, sU, mC0, nC0);

    const float L  = block_sum(loss_acc, red);
    const float WD = block_sum(wd_acc, red);
    const float OT = block_sum(ot_acc, red);
    if (tid == 0) {
        const int slot = b * 2 + (int)rank;
        g_partial[slot][0] = L;
        g_partial[slot][1] = WD;
        g_partial[slot][2] = OT;
    }
    cluster_sync();   // no CTA exits while peer DSMEM ops could be in flight
}

__global__ void finalize_kernel(float* __restrict__ out) {
    const int t = threadIdx.x;
    if (t < 3) {
        float s = 0.f;
#pragma unroll
        for (int i = 0; i < 2 * B_; i++) s += g_partial[i][t];
        out[t] = s;   // (loss, wd, ot_obj)
    }
}

extern "C" void kernel_launch(void* const* d_in, const int* in_sizes, int n_in,
                              void* d_out, int out_size) {
    const float* normed   = (const float*)d_in[0];
    const float* unnormed = (const float*)d_in[1];
    const float* gtd      = (const float*)d_in[2];
    const float* dis      = (const float*)d_in[3];
    // d_in[4] = points (int64), unused.

    cudaFuncSetAttribute(sinkhorn_kernel,
                         cudaFuncAttributeMaxDynamicSharedMemorySize, SMEM_BYTES_);

    precompute_kernel<<<B_ + 1, PTHREADS_>>>(unnormed, gtd, dis);
    sinkhorn_kernel<<<2 * B_, THREADS_, SMEM_BYTES_>>>(normed, unnormed);
    finalize_kernel<<<1, 32>>>((float*)d_out);
}

// round 13
// speedup vs baseline: 2.0384x; 1.1959x over previous
#include <cuda_runtime.h>
#include <cstdint>

// OT_Loss (Sinkhorn, N=9216, B=8, 100 iters), separable kernel K = G (x) G.
// R12: fused precompute, split cluster arrive/wait (hides backpressure barrier
// behind stages 1-3), 64-bit transposed DSMEM exchange, unroll 8.

#define D_        96
#define N_        9216
#define B_        8
#define NITER_    100
#define STR_      100                 // stride for 96-wide matrices
#define SVT_      52                  // stride for 48-wide matrices
#define SRT_      98                  // stride for transposed exchange buffer
#define THREADS_  256

// SMEM layout (floats)
#define OFF_G_   0
#define OFF_GT_  9600
#define OFF_U_   19200
#define OFF_RP_  28800                // peer-incoming partial R (transposed, 96 x 98 = 9408)
#define OFF_V_   38400                // 96 x 48 (stride 52)
#define OFF_T_   43392                // 96 x 48 (stride 52)
#define OFF_W_   48384                // 48 x 96 (stride 100)
#define SMEM_FLOATS_ 53184
#define SMEM_BYTES_  (SMEM_FLOATS_ * sizeof(float))   // 212736 B

__device__ float g_src[B_ * N_];        // softmax(-unnormed), each CTA writes own half
__device__ float g_partial[2 * B_][3];  // per-(batch,rank) (loss, wd, ot)

typedef unsigned long long ull;

// ---------------- f32x2 / PTX helpers ----------------
__device__ __forceinline__ ull dup2(float x) {
    ull d; asm("mov.b64 %0, {%1, %1};" : "=l"(d) : "f"(x)); return d;
}
__device__ __forceinline__ ull fma2(ull a, ull b, ull c) {
    ull d; asm("fma.rn.f32x2 %0, %1, %2, %3;" : "=l"(d) : "l"(a), "l"(b), "l"(c));
    return d;
}
__device__ __forceinline__ float2 unpack2(ull v) {
    float2 r; asm("mov.b64 {%0, %1}, %2;" : "=f"(r.x), "=f"(r.y) : "l"(v)); return r;
}
__device__ __forceinline__ ull ld2(const float* p) {
    return *reinterpret_cast<const ull*>(p);
}
__device__ __forceinline__ uint32_t smem_u32(const void* p) {
    uint32_t a;
    asm("{ .reg .u64 t; cvta.to.shared.u64 t, %1; cvt.u32.u64 %0, t; }"
        : "=r"(a) : "l"(p));
    return a;
}
__device__ __forceinline__ uint32_t mapa_peer(uint32_t addr, uint32_t rank) {
    uint32_t r;
    asm("mapa.shared::cluster.u32 %0, %1, %2;" : "=r"(r) : "r"(addr), "r"(rank));
    return r;
}
__device__ __forceinline__ void st_cluster_u64(uint32_t addr, ull v) {
    asm volatile("st.shared::cluster.u64 [%0], %1;" :: "r"(addr), "l"(v) : "memory");
}
__device__ __forceinline__ void cluster_arrive() {
    asm volatile("barrier.cluster.arrive.aligned;" ::: "memory");
}
__device__ __forceinline__ void cluster_wait() {
    asm volatile("barrier.cluster.wait.aligned;" ::: "memory");
}
__device__ __forceinline__ uint32_t ctarank() {
    uint32_t r; asm("mov.u32 %0, %%cluster_ctarank;" : "=r"(r)); return r;
}

// ---------------- GEMM cores: C[m,n] = sum_k A[k][m] * B[k][n] --------------
// 6x3 tile (3 f32x2 pairs x 3 cols), k+1 prefetch.
template <int K, int LDA, int LDB>
__device__ __forceinline__ void gemm6x3(const float* __restrict__ A,
                                        const float* __restrict__ Bm,
                                        int m0, int n0, ull acc[3][3]) {
#pragma unroll
    for (int t = 0; t < 3; t++)
#pragma unroll
        for (int j = 0; j < 3; j++) acc[t][j] = 0ULL;

    const float* ap = A + m0;
    const float* bp = Bm + n0;
    ull a0 = ld2(ap), a1 = ld2(ap + 2), a2 = ld2(ap + 4);
    float b0 = bp[0], b1 = bp[1], b2 = bp[2];
#pragma unroll 8
    for (int k = 0; k < K - 1; k++) {
        ap += LDA; bp += LDB;
        ull na0 = ld2(ap), na1 = ld2(ap + 2), na2 = ld2(ap + 4);
        float nb0 = bp[0], nb1 = bp[1], nb2 = bp[2];
        ull B0 = dup2(b0), B1 = dup2(b1), B2 = dup2(b2);
        acc[0][0] = fma2(a0, B0, acc[0][0]);
        acc[0][1] = fma2(a0, B1, acc[0][1]);
        acc[0][2] = fma2(a0, B2, acc[0][2]);
        acc[1][0] = fma2(a1, B0, acc[1][0]);
        acc[1][1] = fma2(a1, B1, acc[1][1]);
        acc[1][2] = fma2(a1, B2, acc[1][2]);
        acc[2][0] = fma2(a2, B0, acc[2][0]);
        acc[2][1] = fma2(a2, B1, acc[2][1]);
        acc[2][2] = fma2(a2, B2, acc[2][2]);
        a0 = na0; a1 = na1; a2 = na2; b0 = nb0; b1 = nb1; b2 = nb2;
    }
    ull B0 = dup2(b0), B1 = dup2(b1), B2 = dup2(b2);
    acc[0][0] = fma2(a0, B0, acc[0][0]);
    acc[0][1] = fma2(a0, B1, acc[0][1]);
    acc[0][2] = fma2(a0, B2, acc[0][2]);
    acc[1][0] = fma2(a1, B0, acc[1][0]);
    acc[1][1] = fma2(a1, B1, acc[1][1]);
    acc[1][2] = fma2(a1, B2, acc[1][2]);
    acc[2][0] = fma2(a2, B0, acc[2][0]);
    acc[2][1] = fma2(a2, B1, acc[2][1]);
    acc[2][2] = fma2(a2, B2, acc[2][2]);
}

// 12x3 tile (6 f32x2 pairs via LDS.128), k+1 prefetch.
template <int K, int LDA, int LDB>
__device__ __forceinline__ void gemm12x3(const float* __restrict__ A,
                                         const float* __restrict__ Bm,
                                         int m0, int n0, ull acc[6][3]) {
#pragma unroll
    for (int t = 0; t < 6; t++)
#pragma unroll
        for (int j = 0; j < 3; j++) acc[t][j] = 0ULL;

    const float* ap = A + m0;   // 16B aligned (m0 multiple of 12)
    const float* bp = Bm + n0;
    ulonglong2 p0 = *reinterpret_cast<const ulonglong2*>(ap);
    ulonglong2 p1 = *reinterpret_cast<const ulonglong2*>(ap + 4);
    ulonglong2 p2 = *reinterpret_cast<const ulonglong2*>(ap + 8);
    float b0 = bp[0], b1 = bp[1], b2 = bp[2];
#pragma unroll 4
    for (int k = 0; k < K - 1; k++) {
        ap += LDA; bp += LDB;
        ulonglong2 q0 = *reinterpret_cast<const ulonglong2*>(ap);
        ulonglong2 q1 = *reinterpret_cast<const ulonglong2*>(ap + 4);
        ulonglong2 q2 = *reinterpret_cast<const ulonglong2*>(ap + 8);
        float nb0 = bp[0], nb1 = bp[1], nb2 = bp[2];
        ull B0 = dup2(b0), B1 = dup2(b1), B2 = dup2(b2);
        ull a[6] = {p0.x, p0.y, p1.x, p1.y, p2.x, p2.y};
#pragma unroll
        for (int t = 0; t < 6; t++) {
            acc[t][0] = fma2(a[t], B0, acc[t][0]);
            acc[t][1] = fma2(a[t], B1, acc[t][1]);
            acc[t][2] = fma2(a[t], B2, acc[t][2]);
        }
        p0 = q0; p1 = q1; p2 = q2; b0 = nb0; b1 = nb1; b2 = nb2;
    }
    ull B0 = dup2(b0), B1 = dup2(b1), B2 = dup2(b2);
    ull a[6] = {p0.x, p0.y, p1.x, p1.y, p2.x, p2.y};
#pragma unroll
    for (int t = 0; t < 6; t++) {
        acc[t][0] = fma2(a[t], B0, acc[t][0]);
        acc[t][1] = fma2(a[t], B1, acc[t][1]);
        acc[t][2] = fma2(a[t], B2, acc[t][2]);
    }
}

__device__ __forceinline__ void store6x3(float* __restrict__ C, int ldc,
                                         int m0, int n0, ull acc[3][3]) {
#pragma unroll
    for (int t = 0; t < 3; t++)
#pragma unroll
        for (int j = 0; j < 3; j++) {
            float2 v = unpack2(acc[t][j]);
            C[(m0 + 2 * t)     * ldc + n0 + j] = v.x;
            C[(m0 + 2 * t + 1) * ldc + n0 + j] = v.y;
        }
}

__device__ __forceinline__ float dot12x3(ull acc[6][3],
                                         const float* __restrict__ Um,
                                         int m0, int n0) {
    float s = 0.f;
#pragma unroll
    for (int t = 0; t < 6; t++)
#pragma unroll
        for (int j = 0; j < 3; j++) {
            float2 v = unpack2(acc[t][j]);
            s += v.x * Um[(m0 + 2 * t)     * STR_ + n0 + j];
            s += v.y * Um[(m0 + 2 * t + 1) * STR_ + n0 + j];
        }
    return s;
}

// block reduce (sum) -> valid on tid 0
__device__ __forceinline__ float block_sum(float v, float* red) {
#pragma unroll
    for (int o = 16; o > 0; o >>= 1) v += __shfl_down_sync(0xffffffffu, v, o);
    __syncthreads();
    if ((threadIdx.x & 31) == 0) red[threadIdx.x >> 5] = v;
    __syncthreads();
    if (threadIdx.x == 0) {
        float s = 0.f;
#pragma unroll
        for (int i = 0; i < THREADS_ / 32; i++) s += red[i];
        v = s;
    }
    return v;
}

// block reduce + broadcast to all threads
__device__ __forceinline__ float block_min_bcast(float v, float* red) {
#pragma unroll
    for (int o = 16; o > 0; o >>= 1) v = fminf(v, __shfl_down_sync(0xffffffffu, v, o));
    __syncthreads();
    if ((threadIdx.x & 31) == 0) red[threadIdx.x >> 5] = v;
    __syncthreads();
    if (threadIdx.x == 0) {
        float r = red[0];
#pragma unroll
        for (int i = 1; i < THREADS_ / 32; i++) r = fminf(r, red[i]);
        red[16] = r;
    }
    __syncthreads();
    return red[16];
}
__device__ __forceinline__ float block_sum_bcast(float v, float* red) {
#pragma unroll
    for (int o = 16; o > 0; o >>= 1) v += __shfl_down_sync(0xffffffffu, v, o);
    __syncthreads();
    if ((threadIdx.x & 31) == 0) red[threadIdx.x >> 5] = v;
    __syncthreads();
    if (threadIdx.x == 0) {
        float r = 0.f;
#pragma unroll
        for (int i = 0; i < THREADS_ / 32; i++) r += red[i];
        red[17] = r;
    }
    __syncthreads();
    return red[17];
}

// ---------------- main: 2-CTA cluster per batch (prologue fused) ------------
__global__ void __launch_bounds__(THREADS_, 1) __cluster_dims__(2, 1, 1)
sinkhorn_kernel(const float* __restrict__ normed,
                const float* __restrict__ unnormed,
                const float* __restrict__ gtd,
                const float* __restrict__ dis) {
    extern __shared__ float sm[];
    float* sG  = sm + OFF_G_;    // G (HT in epilogue)
    float* sGT = sm + OFF_GT_;
    float* sU  = sm + OFF_U_;    // full U (replicated)
    float* sRp = sm + OFF_RP_;   // peer-incoming partial R, TRANSPOSED [pb][pa]
    float* sV  = sm + OFF_V_;    // own-half V  [jy][jxl], stride 52
    float* sT  = sm + OFF_T_;    // own-half T  [pb][jxl], stride 52
    float* sW  = sm + OFF_W_;    // own-half W  [jxl][pb], stride 100
    __shared__ float red[32];

    const int      tid  = threadIdx.x;
    const uint32_t rank = ctarank();
    const int      b    = blockIdx.x >> 1;
    const int      jxo  = (int)rank * 48;
    const int      lane = tid & 31;
    const int      w    = tid >> 5;

    // tile maps
    const int mA0 = w * 12 + (lane >> 4) * 6;   // 96-m half-split map
    const int nA0 = (lane & 15) * 3;            // 48-n local
    const int mB0 = w * 6;                      // 48-m map
    const int nB0 = lane * 3;                   // 96-n
    const int mC0 = w * 12;                     // 96-m full map
    const int nC0 = lane * 3;                   // 96-n
    const float eps = 1e-16f;

    // ---- prologue A: G tables from dis (E[i,j] = dis[i, j*96] - dis[0]/2) ----
    const float e00 = 0.5f * __ldg(&dis[0]);
    for (int idx = tid; idx < D_ * D_; idx += THREADS_) {
        const int i = idx / D_, j = idx - i * D_;
        const float e = __ldg(&dis[(size_t)i * N_ + (size_t)j * D_]) - e00;
        const float g = expf(e * (-0.1f));
        sG [i * STR_ + j] = g;
        sGT[j * STR_ + i] = g;
        sU [i * STR_ + j] = 1.0f / 9216.0f;
    }

    // ---- prologue B: softmaxes (redundant per CTA; gmem passes, no scratch) --
    const float* __restrict__ ub = unnormed + b * N_;
    const float* __restrict__ gb = gtd + b * N_;

    float psrc[6][3];    // stage2 epilogue tile
    float ptgt[12][3];   // stage4 epilogue tile
    {
        // src = softmax(-unnormed[b])
        float mn = 3.402823466e38f;
        for (int q = tid; q < N_; q += THREADS_) mn = fminf(mn, __ldg(&ub[q]));
        mn = block_min_bcast(mn, red);
        float sum = 0.f;
        for (int q = tid; q < N_; q += THREADS_) sum += expf(mn - __ldg(&ub[q]));
        const float inv = 1.0f / block_sum_bcast(sum, red);
        // own-half values -> g_src (read back in the loss epilogue)
        float* __restrict__ srcw = g_src + b * N_;
        for (int idx = tid; idx < D_ * 48; idx += THREADS_) {
            const int jy = idx / 48, jxl = idx - jy * 48;
            const int q = jy * D_ + jxo + jxl;
            srcw[q] = expf(mn - __ldg(&ub[q])) * inv;
        }
#pragma unroll
        for (int i = 0; i < 6; i++)
#pragma unroll
            for (int j = 0; j < 3; j++)
                psrc[i][j] = expf(mn - __ldg(&ub[(mA0 + i) * D_ + jxo + nA0 + j])) * inv;

        // tgt = softmax(-gt[b])
        float mt = 3.402823466e38f;
        for (int q = tid; q < N_; q += THREADS_) mt = fminf(mt, __ldg(&gb[q]));
        mt = block_min_bcast(mt, red);
        float sumt = 0.f;
        for (int q = tid; q < N_; q += THREADS_) sumt += expf(mt - __ldg(&gb[q]));
        const float invt = 1.0f / block_sum_bcast(sumt, red);
#pragma unroll
        for (int i = 0; i < 12; i++)
#pragma unroll
            for (int j = 0; j < 3; j++)
                ptgt[i][j] = expf(mt - __ldg(&gb[(mC0 + i) * D_ + nC0 + j])) * invt;
    }
    __syncthreads();

    const uint32_t rp_local = smem_u32(sRp);
    const uint32_t rp_peer  = mapa_peer(rp_local, rank ^ 1u);

    ull acc3[3][3];
    ull acc6[6][3];

    cluster_arrive();   // seed the backpressure phase for iteration 0

    for (int it = 0; it < NITER_; it++) {
        // stage1: T[pb][jxl] = sum_pa U[pa][pb] * G[pa][jxo+jxl]
        gemm6x3<D_, STR_, STR_>(sU, sG + jxo, mA0, nA0, acc3);
        store6x3(sT, SVT_, mA0, nA0, acc3);
        __syncthreads();

        // stage2: S[jy][jxl] = sum_pb G[pb][jy] * T[pb][jxl];  V = src/(S+eps)
        gemm6x3<D_, STR_, SVT_>(sG, sT, mA0, nA0, acc3);
#pragma unroll
        for (int t = 0; t < 3; t++)
#pragma unroll
            for (int j = 0; j < 3; j++) {
                float2 s = unpack2(acc3[t][j]);
                const int r0 = mA0 + 2 * t, c = nA0 + j;
                sV[r0 * SVT_ + c]       = psrc[2 * t][j]     / (s.x + eps);
                sV[(r0 + 1) * SVT_ + c] = psrc[2 * t + 1][j] / (s.y + eps);
            }
        __syncthreads();

        // stage3: W[jxl][pb] = sum_jy V[jy][jxl] * GT[jy][pb]
        gemm6x3<D_, SVT_, STR_>(sV, sGT, mB0, nB0, acc3);
        store6x3(sW, STR_, mB0, nB0, acc3);
        __syncthreads();

        // stage4 (partial): Rr[pa][pb] = sum_{jxl} GT[jxo+jxl][pa] * W[jxl][pb]
        gemm12x3<48, STR_, STR_>(sGT + (size_t)jxo * STR_, sW, mC0, nC0, acc6);

        // backpressure wait: pairs the "reads done" arrive from prev iteration
        // (posted ~3 GEMM stages ago -> effectively free)
        cluster_wait();
        // 64-bit transposed remote store of own partial tile
#pragma unroll
        for (int t = 0; t < 6; t++)
#pragma unroll
            for (int j = 0; j < 3; j++)
                st_cluster_u64(rp_peer + 4u * ((uint32_t)((nC0 + j) * SRT_ + mC0 + 2 * t)),
                               acc6[t][j]);
        cluster_arrive();   // release stores
        cluster_wait();     // acquire peer's stores

        // U = tgt / (own partial + peer partial + eps)
#pragma unroll
        for (int t = 0; t < 6; t++)
#pragma unroll
            for (int j = 0; j < 3; j++) {
                const int r0 = mC0 + 2 * t, c = nC0 + j;
                float2 v = unpack2(acc6[t][j]);
                float2 p = unpack2(ld2(sRp + c * SRT_ + r0));
                sU[r0 * STR_ + c]       = ptgt[2 * t][j]     / (v.x + p.x + eps);
                sU[(r0 + 1) * STR_ + c] = ptgt[2 * t + 1][j] / (v.y + p.y + eps);
            }
        cluster_arrive();   // my sRp reads done (peer may store next iteration)
        __syncthreads();
    }
    cluster_wait();         // balance final arrive; no remote ops after this
    // Final: sU = u (full), sV = v (own half), sW = W(final v, own half).

    // ot / loss partials over own jx half
    float ot_acc = 0.f, loss_acc = 0.f;
    {
        const float* __restrict__ nb   = normed + b * N_;
        const float* __restrict__ srcb = g_src + b * N_;
        for (int idx = tid; idx < D_ * 48; idx += THREADS_) {
            const int jy = idx / 48, jxl = idx - jy * 48;
            const int q = jy * D_ + jxo + jxl;
            const float v    = sV[jy * SVT_ + jxl];
            const float beta = 10.0f * logf(v + eps);
            ot_acc += __ldg(&nb[q]) * beta;
            const float s = srcb[q];
            loss_acc += __ldg(&ub[q]) * (-s * (1.0f + s) * beta);
        }
    }

    // wd partials: M = H(x)G + G(x)H, H = E.*G.  Regenerate HT over sG:
    // HT[a][b] = Gt[a][b] * (-10 * ln(Gt[a][b]))   (E = -10 ln G, exact to fp32)
    for (int idx = tid; idx < D_ * D_; idx += THREADS_) {
        const int i = idx / D_, j = idx - i * D_;
        const float g = sGT[i * STR_ + j];
        sG[i * STR_ + j] = g * (-10.0f * logf(g));
    }
    __syncthreads();

    // R2 partial: sum_{jxl} HT[jxo+jxl][pa] * W[jxl][pb]
    gemm12x3<48, STR_, STR_>(sG + (size_t)jxo * STR_, sW, mC0, nC0, acc6);
    float wd_acc = dot12x3(acc6, sU, mC0, nC0);
    __syncthreads();   // before overwriting sW

    // W2[jxl][pb] = sum_jy V[jy][jxl] * HT[jy][pb]
    gemm6x3<D_, SVT_, STR_>(sV, sG, mB0, nB0, acc3);
    store6x3(sW, STR_, mB0, nB0, acc3);
    __syncthreads();

    // R1 partial: sum_{jxl} GT[jxo+jxl][pa] * W2[jxl][pb]
    gemm12x3<48, STR_, STR_>(sGT + (size_t)jxo * STR_, sW, mC0, nC0, acc6);
    wd_acc += dot12x3(acc6, sU, mC0, nC0);

    const float L  = block_sum(loss_acc, red);
    const float WD = block_sum(wd_acc, red);
    const float OT = block_sum(ot_acc, red);
    if (tid == 0) {
        const int slot = b * 2 + (int)rank;
        g_partial[slot][0] = L;
        g_partial[slot][1] = WD;
        g_partial[slot][2] = OT;
    }
}

__global__ void finalize_kernel(float* __restrict__ out) {
    const int t = threadIdx.x;
    if (t < 3) {
        float s = 0.f;
#pragma unroll
        for (int i = 0; i < 2 * B_; i++) s += g_partial[i][t];
        out[t] = s;   // (loss, wd, ot_obj)
    }
}

extern "C" void kernel_launch(void* const* d_in, const int* in_sizes, int n_in,
                              void* d_out, int out_size) {
    const float* normed   = (const float*)d_in[0];
    const float* unnormed = (const float*)d_in[1];
    const float* gtd      = (const float*)d_in[2];
    const float* dis      = (const float*)d_in[3];
    // d_in[4] = points (int64), unused.

    cudaFuncSetAttribute(sinkhorn_kernel,
                         cudaFuncAttributeMaxDynamicSharedMemorySize, SMEM_BYTES_);

    sinkhorn_kernel<<<2 * B_, THREADS_, SMEM_BYTES_>>>(normed, unnormed, gtd, dis);
    finalize_kernel<<<1, 32>>>((float*)d_out);
}

// round 14
// speedup vs baseline: 3.1489x; 1.5448x over previous
#include <cuda_runtime.h>
#include <cstdint>

// OT_Loss (Sinkhorn, N=9216, B=8, 100 iters), separable kernel K = G (x) G.
// R13: 4-CTA cluster per batch, jx-quarter split. Stages 1-3 use 6x3 tiles with
// 2-thread interleaved k-split (shfl-combined). Stage4 partial R reduce-scatter
// + U all-gather over DSMEM. rcp.approx for all divisions.

#define D_       96
#define NQ_      24
#define N_       9216
#define B_       8
#define CL_      4
#define NITER_   100
#define SF_      100     // stride, 96-wide matrices
#define SQ_      28      // stride, 24-wide / transposed-slice matrices
#define THREADS_ 256

// SMEM layout (floats)
#define OFF_G_    0        // G [pa][*]  (HT in epilogue), 96x100
#define OFF_GT_   9600     // G^T, 96x100
#define OFF_U_    19200    // full U [pa][pb], 96x100
#define OFF_W_    28800    // own W quarter [jxl][pb], 24x100
#define OFF_V_    31200    // own V quarter [jy][jxl], 96x28
#define OFF_T_    33888    // own T quarter [pb][jxl], 96x28
#define OFF_ROWN_ 36576    // own partial of own R-slice, transposed [pb][rl], 96x28
#define OFF_RIN_  39264    // 3 incoming partials of own R-slice, 3 x 96x28
#define SMEM_FLOATS_ 47328
#define SMEM_BYTES_  (SMEM_FLOATS_ * 4)   // 189312 B

__device__ float g_src[B_ * N_];            // softmax(-unnormed); each CTA writes own quarter
__device__ float g_partial[CL_ * B_][3];    // per-(batch,rank) (loss, wd, ot)

typedef unsigned long long ull;

// ---------------- f32x2 / PTX helpers ----------------
__device__ __forceinline__ ull dup2(float x) {
    ull d; asm("mov.b64 %0, {%1, %1};" : "=l"(d) : "f"(x)); return d;
}
__device__ __forceinline__ ull fma2(ull a, ull b, ull c) {
    ull d; asm("fma.rn.f32x2 %0, %1, %2, %3;" : "=l"(d) : "l"(a), "l"(b), "l"(c));
    return d;
}
__device__ __forceinline__ float2 unpack2(ull v) {
    float2 r; asm("mov.b64 {%0, %1}, %2;" : "=f"(r.x), "=f"(r.y) : "l"(v)); return r;
}
__device__ __forceinline__ ull ld2(const float* p) {
    return *reinterpret_cast<const ull*>(p);
}
__device__ __forceinline__ float rcpa(float x) {
    float r; asm("rcp.approx.ftz.f32 %0, %1;" : "=f"(r) : "f"(x)); return r;
}
__device__ __forceinline__ uint32_t smem_u32(const void* p) {
    uint32_t a;
    asm("{ .reg .u64 t; cvta.to.shared.u64 t, %1; cvt.u32.u64 %0, t; }"
        : "=r"(a) : "l"(p));
    return a;
}
__device__ __forceinline__ uint32_t mapa_peer(uint32_t addr, uint32_t rank) {
    uint32_t r;
    asm("mapa.shared::cluster.u32 %0, %1, %2;" : "=r"(r) : "r"(addr), "r"(rank));
    return r;
}
__device__ __forceinline__ void st_cluster_u64(uint32_t addr, ull v) {
    asm volatile("st.shared::cluster.u64 [%0], %1;" :: "r"(addr), "l"(v) : "memory");
}
__device__ __forceinline__ void st_cluster_u32(uint32_t addr, float v) {
    asm volatile("st.shared::cluster.f32 [%0], %1;" :: "r"(addr), "f"(v) : "memory");
}
__device__ __forceinline__ void cluster_sync_() {
    asm volatile("barrier.cluster.arrive.aligned;" ::: "memory");
    asm volatile("barrier.cluster.wait.aligned;"   ::: "memory");
}
__device__ __forceinline__ uint32_t ctarank() {
    uint32_t r; asm("mov.u32 %0, %%cluster_ctarank;" : "=r"(r)); return r;
}

// ---------------- GEMM cores: C[m,n] = sum_k A[k][m] * B[k][n] --------------
// 6x3 tile (3 f32x2 pairs x 3 cols), k+1 prefetch. LDA/LDB are PER-STEP strides
// (pass 2x the matrix stride for interleaved k-split).
template <int K, int LDA, int LDB>
__device__ __forceinline__ void gemm6x3(const float* __restrict__ A,
                                        const float* __restrict__ Bm,
                                        int m0, int n0, ull acc[3][3]) {
#pragma unroll
    for (int t = 0; t < 3; t++)
#pragma unroll
        for (int j = 0; j < 3; j++) acc[t][j] = 0ULL;

    const float* ap = A + m0;
    const float* bp = Bm + n0;
    ull a0 = ld2(ap), a1 = ld2(ap + 2), a2 = ld2(ap + 4);
    float b0 = bp[0], b1 = bp[1], b2 = bp[2];
#pragma unroll 8
    for (int k = 0; k < K - 1; k++) {
        ap += LDA; bp += LDB;
        ull na0 = ld2(ap), na1 = ld2(ap + 2), na2 = ld2(ap + 4);
        float nb0 = bp[0], nb1 = bp[1], nb2 = bp[2];
        ull B0 = dup2(b0), B1 = dup2(b1), B2 = dup2(b2);
        acc[0][0] = fma2(a0, B0, acc[0][0]);
        acc[0][1] = fma2(a0, B1, acc[0][1]);
        acc[0][2] = fma2(a0, B2, acc[0][2]);
        acc[1][0] = fma2(a1, B0, acc[1][0]);
        acc[1][1] = fma2(a1, B1, acc[1][1]);
        acc[1][2] = fma2(a1, B2, acc[1][2]);
        acc[2][0] = fma2(a2, B0, acc[2][0]);
        acc[2][1] = fma2(a2, B1, acc[2][1]);
        acc[2][2] = fma2(a2, B2, acc[2][2]);
        a0 = na0; a1 = na1; a2 = na2; b0 = nb0; b1 = nb1; b2 = nb2;
    }
    ull B0 = dup2(b0), B1 = dup2(b1), B2 = dup2(b2);
    acc[0][0] = fma2(a0, B0, acc[0][0]);
    acc[0][1] = fma2(a0, B1, acc[0][1]);
    acc[0][2] = fma2(a0, B2, acc[0][2]);
    acc[1][0] = fma2(a1, B0, acc[1][0]);
    acc[1][1] = fma2(a1, B1, acc[1][1]);
    acc[1][2] = fma2(a1, B2, acc[1][2]);
    acc[2][0] = fma2(a2, B0, acc[2][0]);
    acc[2][1] = fma2(a2, B1, acc[2][1]);
    acc[2][2] = fma2(a2, B2, acc[2][2]);
}

// k-split combine: partner lane^16 holds the other k-parity partial.
__device__ __forceinline__ void combine_ks(ull acc[3][3], float c[6][3]) {
#pragma unroll
    for (int t = 0; t < 3; t++)
#pragma unroll
        for (int j = 0; j < 3; j++) {
            float2 v = unpack2(acc[t][j]);
            c[2 * t][j]     = v.x + __shfl_xor_sync(0xffffffffu, v.x, 16);
            c[2 * t + 1][j] = v.y + __shfl_xor_sync(0xffffffffu, v.y, 16);
        }
}

// 12x3 tile (6 f32x2 pairs via LDS.128), k+1 prefetch. No k-split.
template <int K, int LDA, int LDB>
__device__ __forceinline__ void gemm12x3(const float* __restrict__ A,
                                         const float* __restrict__ Bm,
                                         int m0, int n0, ull acc[6][3]) {
#pragma unroll
    for (int t = 0; t < 6; t++)
#pragma unroll
        for (int j = 0; j < 3; j++) acc[t][j] = 0ULL;

    const float* ap = A + m0;   // 16B aligned (m0 multiple of 12)
    const float* bp = Bm + n0;
    ulonglong2 p0 = *reinterpret_cast<const ulonglong2*>(ap);
    ulonglong2 p1 = *reinterpret_cast<const ulonglong2*>(ap + 4);
    ulonglong2 p2 = *reinterpret_cast<const ulonglong2*>(ap + 8);
    float b0 = bp[0], b1 = bp[1], b2 = bp[2];
#pragma unroll 4
    for (int k = 0; k < K - 1; k++) {
        ap += LDA; bp += LDB;
        ulonglong2 q0 = *reinterpret_cast<const ulonglong2*>(ap);
        ulonglong2 q1 = *reinterpret_cast<const ulonglong2*>(ap + 4);
        ulonglong2 q2 = *reinterpret_cast<const ulonglong2*>(ap + 8);
        float nb0 = bp[0], nb1 = bp[1], nb2 = bp[2];
        ull B0 = dup2(b0), B1 = dup2(b1), B2 = dup2(b2);
        ull a[6] = {p0.x, p0.y, p1.x, p1.y, p2.x, p2.y};
#pragma unroll
        for (int t = 0; t < 6; t++) {
            acc[t][0] = fma2(a[t], B0, acc[t][0]);
            acc[t][1] = fma2(a[t], B1, acc[t][1]);
            acc[t][2] = fma2(a[t], B2, acc[t][2]);
        }
        p0 = q0; p1 = q1; p2 = q2; b0 = nb0; b1 = nb1; b2 = nb2;
    }
    ull B0 = dup2(b0), B1 = dup2(b1), B2 = dup2(b2);
    ull a[6] = {p0.x, p0.y, p1.x, p1.y, p2.x, p2.y};
#pragma unroll
    for (int t = 0; t < 6; t++) {
        acc[t][0] = fma2(a[t], B0, acc[t][0]);
        acc[t][1] = fma2(a[t], B1, acc[t][1]);
        acc[t][2] = fma2(a[t], B2, acc[t][2]);
    }
}

__device__ __forceinline__ float dot12x3(ull acc[6][3],
                                         const float* __restrict__ Um,
                                         int m0, int n0) {
    float s = 0.f;
#pragma unroll
    for (int t = 0; t < 6; t++)
#pragma unroll
        for (int j = 0; j < 3; j++) {
            float2 v = unpack2(acc[t][j]);
            s += v.x * Um[(m0 + 2 * t)     * SF_ + n0 + j];
            s += v.y * Um[(m0 + 2 * t + 1) * SF_ + n0 + j];
        }
    return s;
}

// ---------------- block reductions ----------------
__device__ __forceinline__ float block_sum(float v, float* red) {
#pragma unroll
    for (int o = 16; o > 0; o >>= 1) v += __shfl_down_sync(0xffffffffu, v, o);
    __syncthreads();
    if ((threadIdx.x & 31) == 0) red[threadIdx.x >> 5] = v;
    __syncthreads();
    if (threadIdx.x == 0) {
        float s = 0.f;
#pragma unroll
        for (int i = 0; i < THREADS_ / 32; i++) s += red[i];
        v = s;
    }
    return v;
}
__device__ __forceinline__ float block_min_bcast(float v, float* red) {
#pragma unroll
    for (int o = 16; o > 0; o >>= 1) v = fminf(v, __shfl_down_sync(0xffffffffu, v, o));
    __syncthreads();
    if ((threadIdx.x & 31) == 0) red[threadIdx.x >> 5] = v;
    __syncthreads();
    if (threadIdx.x == 0) {
        float r = red[0];
#pragma unroll
        for (int i = 1; i < THREADS_ / 32; i++) r = fminf(r, red[i]);
        red[16] = r;
    }
    __syncthreads();
    return red[16];
}
__device__ __forceinline__ float block_sum_bcast(float v, float* red) {
#pragma unroll
    for (int o = 16; o > 0; o >>= 1) v += __shfl_down_sync(0xffffffffu, v, o);
    __syncthreads();
    if ((threadIdx.x & 31) == 0) red[threadIdx.x >> 5] = v;
    __syncthreads();
    if (threadIdx.x == 0) {
        float r = 0.f;
#pragma unroll
        for (int i = 0; i < THREADS_ / 32; i++) r += red[i];
        red[17] = r;
    }
    __syncthreads();
    return red[17];
}

// ---------------- main: 4-CTA cluster per batch ----------------
__global__ void __launch_bounds__(THREADS_, 1) __cluster_dims__(CL_, 1, 1)
sinkhorn_kernel(const float* __restrict__ normed,
                const float* __restrict__ unnormed,
                const float* __restrict__ gtd,
                const float* __restrict__ dis) {
    extern __shared__ float sm[];
    float* sG    = sm + OFF_G_;
    float* sGT   = sm + OFF_GT_;
    float* sU    = sm + OFF_U_;
    float* sW    = sm + OFF_W_;
    float* sV    = sm + OFF_V_;
    float* sT    = sm + OFF_T_;
    float* sRown = sm + OFF_ROWN_;
    float* sRin  = sm + OFF_RIN_;
    __shared__ float red[32];

    const int      tid  = threadIdx.x;
    const uint32_t rank = ctarank();
    const int      b    = blockIdx.x >> 2;
    const int      jxo  = (int)rank * NQ_;
    const int      lane = tid & 31;
    const int      w    = tid >> 5;
    const int      kb   = lane >> 4;     // k-parity for split GEMMs
    const int      sub  = lane & 15;
    const int      tile = w * 16 + sub;
    const float    eps  = 1e-16f;

    // tile maps
    const int m0A = 6 * (tile >> 3), n0A = 3 * (tile & 7);          // 96x24 (stages 1,2)
    const int m0C = 6 * (w >> 1),    n0C = 3 * (16 * (w & 1) + sub); // 24x96 (stage 3, W2)
    const int mD  = 12 * w,          nD  = 3 * lane;                 // 96x96 (stage 4, R1, R2)

    // ---- prologue A: G tables + U init ----
    const float e00 = 0.5f * __ldg(&dis[0]);
    for (int idx = tid; idx < D_ * D_; idx += THREADS_) {
        const int i = idx / D_, j = idx - i * D_;
        const float e = __ldg(&dis[(size_t)i * N_ + (size_t)j * D_]) - e00;
        const float g = expf(e * (-0.1f));
        sG [i * SF_ + j] = g;
        sGT[j * SF_ + i] = g;
        sU [i * SF_ + j] = 1.0f / 9216.0f;
    }

    // ---- prologue B: softmaxes + hoisted tiles ----
    const float* __restrict__ ub = unnormed + b * N_;
    const float* __restrict__ gb = gtd + b * N_;

    float psrc[6][3];     // stage2 epilogue tile (rows m0A.., cols jxo+n0A..)
    float ptgt9[9];       // U-update values
    int   roff[9], uoff[9];
    {
        // src = softmax(-unnormed[b])
        float mn = 3.402823466e38f;
        for (int q = tid; q < N_; q += THREADS_) mn = fminf(mn, __ldg(&ub[q]));
        mn = block_min_bcast(mn, red);
        float sum = 0.f;
        for (int q = tid; q < N_; q += THREADS_) sum += expf(mn - __ldg(&ub[q]));
        const float inv = 1.0f / block_sum_bcast(sum, red);
        float* __restrict__ srcw = g_src + b * N_;
        for (int idx = tid; idx < D_ * NQ_; idx += THREADS_) {
            const int jy = idx / NQ_, jxl = idx - jy * NQ_;
            const int q = jy * D_ + jxo + jxl;
            srcw[q] = expf(mn - __ldg(&ub[q])) * inv;
        }
#pragma unroll
        for (int i = 0; i < 6; i++)
#pragma unroll
            for (int j = 0; j < 3; j++)
                psrc[i][j] = expf(mn - __ldg(&ub[(m0A + i) * D_ + jxo + n0A + j])) * inv;

        // tgt = softmax(-gt[b])
        float mt = 3.402823466e38f;
        for (int q = tid; q < N_; q += THREADS_) mt = fminf(mt, __ldg(&gb[q]));
        mt = block_min_bcast(mt, red);
        float sumt = 0.f;
        for (int q = tid; q < N_; q += THREADS_) sumt += expf(mt - __ldg(&gb[q]));
        const float invt = 1.0f / block_sum_bcast(sumt, red);
#pragma unroll
        for (int s = 0; s < 9; s++) {
            const int idx = tid + 256 * s;          // over own 24x96 R/U slice
            const int rl = idx / D_, cc = idx - rl * D_;
            roff[s] = cc * SQ_ + rl;                // transposed partial-R buffers
            uoff[s] = (NQ_ * (int)rank + rl) * SF_ + cc;
            ptgt9[s] = expf(mt - __ldg(&gb[(NQ_ * (int)rank + rl) * D_ + cc])) * invt;
        }
    }
    __syncthreads();

    // DSMEM destinations
    const int p4 = w >> 1;                          // stage4 destination rank for this warp
    const int rloc4 = 12 * (w & 1);                 // local row within destination slice
    uint32_t dstR = 0;
    if (p4 != (int)rank) {
        const int slot = ((int)rank < p4) ? (int)rank : (int)rank - 1;
        dstR = mapa_peer(smem_u32(sRin + slot * (D_ * SQ_)), (uint32_t)p4);
    }
    uint32_t peerU[3];
    {
        const uint32_t u32U = smem_u32(sU);
        int pi = 0;
        for (int p = 0; p < CL_; p++)
            if (p != (int)rank) peerU[pi++] = mapa_peer(u32U, (uint32_t)p);
    }

    ull acc3[3][3];
    ull acc6[6][3];
    float c[6][3];

    for (int it = 0; it < NITER_; it++) {
        // stage1: T[pb][jxl] = sum_pa U[pa][pb] * G[pa][jxo+jxl]   (k-split over pa)
        gemm6x3<48, 2 * SF_, 2 * SF_>(sU + kb * SF_, sG + kb * SF_ + jxo, m0A, n0A, acc3);
        combine_ks(acc3, c);
        if (!kb)
#pragma unroll
            for (int i = 0; i < 6; i++)
#pragma unroll
                for (int j = 0; j < 3; j++)
                    sT[(m0A + i) * SQ_ + n0A + j] = c[i][j];
        __syncthreads();

        // stage2: S[jy][jxl] = sum_pb G[pb][jy] * T[pb][jxl];  V = src * rcp(S+eps)
        gemm6x3<48, 2 * SF_, 2 * SQ_>(sG + kb * SF_, sT + kb * SQ_, m0A, n0A, acc3);
        combine_ks(acc3, c);
        if (!kb)
#pragma unroll
            for (int i = 0; i < 6; i++)
#pragma unroll
                for (int j = 0; j < 3; j++)
                    sV[(m0A + i) * SQ_ + n0A + j] = psrc[i][j] * rcpa(c[i][j] + eps);
        __syncthreads();

        // stage3: W[jxl][pb] = sum_jy V[jy][jxl] * GT[jy][pb]   (k-split over jy)
        gemm6x3<48, 2 * SQ_, 2 * SF_>(sV + kb * SQ_, sGT + kb * SF_, m0C, n0C, acc3);
        combine_ks(acc3, c);
        if (!kb)
#pragma unroll
            for (int i = 0; i < 6; i++)
#pragma unroll
                for (int j = 0; j < 3; j++)
                    sW[(m0C + i) * SF_ + n0C + j] = c[i][j];
        __syncthreads();

        // stage4: partial R[pa][pb] = sum_jxl GT[jxo+jxl][pa] * W[jxl][pb], k=24
        gemm12x3<NQ_, SF_, SF_>(sGT + jxo * SF_, sW, mD, nD, acc6);

        // reduce-scatter: warp w's rows [12w,12w+12) belong to rank p4's slice
        if (p4 == (int)rank) {
#pragma unroll
            for (int t = 0; t < 6; t++)
#pragma unroll
                for (int j = 0; j < 3; j++)
                    *reinterpret_cast<ull*>(sRown + (nD + j) * SQ_ + rloc4 + 2 * t) = acc6[t][j];
        } else {
#pragma unroll
            for (int t = 0; t < 6; t++)
#pragma unroll
                for (int j = 0; j < 3; j++)
                    st_cluster_u64(dstR + 4u * (uint32_t)((nD + j) * SQ_ + rloc4 + 2 * t),
                                   acc6[t][j]);
        }
        cluster_sync_();   // B1: all partial slices delivered

        // U slice: own 24 rows = tgt * rcp(sum of 4 partials + eps); push to all
#pragma unroll
        for (int s = 0; s < 9; s++) {
            const int ro = roff[s];
            float rs = sRown[ro] + sRin[ro] + sRin[D_ * SQ_ + ro] + sRin[2 * D_ * SQ_ + ro];
            const float u = ptgt9[s] * rcpa(rs + eps);
            sU[uoff[s]] = u;
            st_cluster_u32(peerU[0] + 4u * (uint32_t)uoff[s], u);
            st_cluster_u32(peerU[1] + 4u * (uint32_t)uoff[s], u);
            st_cluster_u32(peerU[2] + 4u * (uint32_t)uoff[s], u);
        }
        cluster_sync_();   // B2: full U assembled everywhere
    }
    // Final: sU = u (full), sV = v (own quarter), sW = W(final v, own quarter).

    // ot / loss partials over own jx quarter
    float ot_acc = 0.f, loss_acc = 0.f;
    {
        const float* __restrict__ nb   = normed + b * N_;
        const float* __restrict__ srcb = g_src + b * N_;
        for (int idx = tid; idx < D_ * NQ_; idx += THREADS_) {
            const int jy = idx / NQ_, jxl = idx - jy * NQ_;
            const int q = jy * D_ + jxo + jxl;
            const float v    = sV[jy * SQ_ + jxl];
            const float beta = 10.0f * logf(v + eps);
            ot_acc += __ldg(&nb[q]) * beta;
            const float s = srcb[q];
            loss_acc += __ldg(&ub[q]) * (-s * (1.0f + s) * beta);
        }
    }

    // wd partials: M = H(x)G + G(x)H, H = E.*G. Regenerate HT over sG.
    for (int idx = tid; idx < D_ * D_; idx += THREADS_) {
        const int i = idx / D_, j = idx - i * D_;
        const float g = sGT[i * SF_ + j];
        sG[i * SF_ + j] = g * (-10.0f * logf(g));
    }
    __syncthreads();

    // R2 partial: sum_jxl HT[jxo+jxl][pa] * W[jxl][pb]
    gemm12x3<NQ_, SF_, SF_>(sG + jxo * SF_, sW, mD, nD, acc6);
    float wd_acc = dot12x3(acc6, sU, mD, nD);
    __syncthreads();   // before overwriting sW

    // W2[jxl][pb] = sum_jy V[jy][jxl] * HT[jy][pb]   (k-split)
    gemm6x3<48, 2 * SQ_, 2 * SF_>(sV + kb * SQ_, sG + kb * SF_, m0C, n0C, acc3);
    combine_ks(acc3, c);
    if (!kb)
#pragma unroll
        for (int i = 0; i < 6; i++)
#pragma unroll
            for (int j = 0; j < 3; j++)
                sW[(m0C + i) * SF_ + n0C + j] = c[i][j];
    __syncthreads();

    // R1 partial: sum_jxl GT[jxo+jxl][pa] * W2[jxl][pb]
    gemm12x3<NQ_, SF_, SF_>(sGT + jxo * SF_, sW, mD, nD, acc6);
    wd_acc += dot12x3(acc6, sU, mD, nD);

    const float L  = block_sum(loss_acc, red);
    const float WD = block_sum(wd_acc, red);
    const float OT = block_sum(ot_acc, red);
    if (tid == 0) {
        const int slot = b * CL_ + (int)rank;
        g_partial[slot][0] = L;
        g_partial[slot][1] = WD;
        g_partial[slot][2] = OT;
    }
}

__global__ void finalize_kernel(float* __restrict__ out) {
    const int t = threadIdx.x;
    if (t < 3) {
        float s = 0.f;
#pragma unroll
        for (int i = 0; i < CL_ * B_; i++) s += g_partial[i][t];
        out[t] = s;   // (loss, wd, ot_obj)
    }
}

extern "C" void kernel_launch(void* const* d_in, const int* in_sizes, int n_in,
                              void* d_out, int out_size) {
    const float* normed   = (const float*)d_in[0];
    const float* unnormed = (const float*)d_in[1];
    const float* gtd      = (const float*)d_in[2];
    const float* dis      = (const float*)d_in[3];
    // d_in[4] = points (int64), unused.

    cudaFuncSetAttribute(sinkhorn_kernel,
                         cudaFuncAttributeMaxDynamicSharedMemorySize, SMEM_BYTES_);

    sinkhorn_kernel<<<CL_ * B_, THREADS_, SMEM_BYTES_>>>(normed, unnormed, gtd, dis);
    finalize_kernel<<<1, 32>>>((float*)d_out);
}